// round 11
// baseline (speedup 1.0000x reference)
#include <cuda_runtime.h>
#include <cstdint>

#define D 256
#define Lh 64
#define Bh 2
#define Nh 10
#define NQh 50
#define Mh 1000
#define NSUP 20
#define NQRY 100
#define NTILE 120
#define PITCH 260
#define PA 68
#define TILE_ELEMS (Lh*D)

// ---------------- scratch (device globals; no allocations allowed) ----------------
__device__ float g_sN[NSUP*TILE_ELEMS];
__device__ float g_qN[NQRY*TILE_ELEMS];
__device__ float g_W1T[4*D*D];                    // W1 transposed (for MLP head)
__device__ float4 g_Wm4[16*4*32*32];              // proj_W bf16 hi/lo b-fragments (1MB)
__device__ float4 g_baseF[NTILE*4*32*32];         // base = x@W0^T + b, fragment-native fp32
__device__ float g_Y1f[NTILE*TILE_ELEMS];         // scratch: Y1 = x@W1blk fp32
__device__ uint2 g_Y1sp[NTILE*256*32];            // Y1 split bf16 hi/lo, [tile][d][kpair]
__device__ uint4 g_AspH[NTILE*4*16*32];           // tile A-fragments (hi) for att GEMM
__device__ uint4 g_AspL[NTILE*4*16*32];           // tile A-fragments (lo)
__device__ uint4 g_BspS[NTILE*8*16*32];           // tile B-fragments (n=seq,k=d) for att GEMM
__device__ uint2 g_XspD[NTILE*256*32];            // tile B-fragments (n=d,k=seq) for pv GEMM
__device__ float4 g_c2scr[2000*4*32*32];          // per-side proj init (base + Y1 term), 131MB
__device__ float g_pool[Mh*1024];                 // pooled+LN'd cat vectors
__device__ float g_logits[Mh];

// Shared-memory layout (floats) for the pair kernel: 22088 floats = 88.4KB
#define SM_A    0
#define SM_ATT  (SM_A + Lh*PITCH)
#define SM_PMAX (SM_ATT + Lh*PA)
#define SM_PSUM (SM_PMAX + D)
#define SM_POOL (SM_PSUM + D)       // 512
#define SM_SCAL (SM_POOL + 512)     // 64 (rsum or csum reciprocal)
#define SM_RED  (SM_SCAL + 64)
#define SM_TOTAL (SM_RED + 8)
#define SMEM_PAIR_BYTES (SM_TOTAL*4)
#define SMEM_BASE_BYTES (Lh*PITCH*4)

// ---------------- bf16 split helpers ----------------
__device__ __forceinline__ unsigned pack2(float x0, float x1){
    unsigned r; asm("cvt.rn.bf16x2.f32 %0, %1, %2;" : "=r"(r) : "f"(x1), "f"(x0)); return r;
}
__device__ __forceinline__ void split2(float x0, float x1, unsigned &h, unsigned &l){
    h = pack2(x0, x1);
    float h0 = __uint_as_float(h << 16);
    float h1 = __uint_as_float(h & 0xffff0000u);
    l = pack2(x0 - h0, x1 - h1);
}
__device__ __forceinline__ void mmab(float* c, const unsigned* a, const unsigned* b){
    asm volatile("mma.sync.aligned.m16n8k16.row.col.f32.bf16.bf16.f32 "
        "{%0,%1,%2,%3}, {%4,%5,%6,%7}, {%8,%9}, {%0,%1,%2,%3};\n"
        : "+f"(c[0]), "+f"(c[1]), "+f"(c[2]), "+f"(c[3])
        : "r"(a[0]), "r"(a[1]), "r"(a[2]), "r"(a[3]), "r"(b[0]), "r"(b[1]));
}
__device__ __forceinline__ void mma3(float* c, const unsigned* ah, const unsigned* al,
                                     const unsigned* bh, const unsigned* bl){
    mmab(c, ah, bh); mmab(c, ah, bl); mmab(c, al, bh);
}

__device__ __forceinline__ float mishf(float x){
    if (x > 20.0f) return x;
    float u = __expf(x);
    float v = u*u + 2.0f*u;
    return x * v / (v + 2.0f);
}

// block-wide sum over 256 threads (8 warps)
__device__ __forceinline__ float blockSum256(float v, float* red, int t){
    #pragma unroll
    for (int o = 16; o > 0; o >>= 1) v += __shfl_xor_sync(0xffffffffu, v, o);
    if ((t & 31) == 0) red[t >> 5] = v;
    __syncthreads();
    float s = red[0]+red[1]+red[2]+red[3]+red[4]+red[5]+red[6]+red[7];
    __syncthreads();
    return s;
}

// ---------------- kernel A: row LayerNorm of support & query ----------------
__global__ void k_ln(const float* __restrict__ sup, const float* __restrict__ qry,
                     const float* __restrict__ gg, const float* __restrict__ bb){
    __shared__ float rs[8], rq[8];
    int r = blockIdx.x, t = threadIdx.x;
    const float* src; float* dst;
    const int nsr = NSUP*Lh;
    if (r < nsr){ src = sup + (size_t)r*D; dst = g_sN + (size_t)r*D; }
    else        { src = qry + (size_t)(r-nsr)*D; dst = g_qN + (size_t)(r-nsr)*D; }
    float x = src[t];
    float s = x, q = x*x;
    #pragma unroll
    for (int o = 16; o > 0; o >>= 1){
        s += __shfl_xor_sync(0xffffffffu, s, o);
        q += __shfl_xor_sync(0xffffffffu, q, o);
    }
    if ((t & 31) == 0){ rs[t>>5] = s; rq[t>>5] = q; }
    __syncthreads();
    float S = 0.f, Q2 = 0.f;
    #pragma unroll
    for (int w = 0; w < 8; w++){ S += rs[w]; Q2 += rq[w]; }
    float mu  = S  * (1.0f/D);
    float var = Q2 * (1.0f/D) - mu*mu;
    float inv = rsqrtf(var + 1e-5f);
    dst[t] = (x - mu)*inv*gg[t] + bb[t];
}

// ---------------- kernel B: transpose W1 [256][1024] -> [1024][256] ----------------
__global__ void k_transposeW1(const float* __restrict__ W){
    int c = blockIdx.x, j = threadIdx.x;
    g_W1T[c*D + j] = W[(size_t)j*1024 + c];
}

// ---------------- kernel B2: proj_W -> bf16 hi/lo b-fragments ----------------
__global__ void k_prepw(const float* __restrict__ pw){
    int idx = blockIdx.x*256 + threadIdx.x;     // 65536 total
    int lane = idx & 31;
    int jt   = (idx >> 5) & 31;
    int w    = (idx >> 10) & 3;
    int kb   = idx >> 12;
    int tig = lane & 3, gid = lane >> 2;
    int j = jt*8 + gid;
    int cblk = (w == 3) ? 0 : (w + 1);
    size_t base = (size_t)j*1024 + cblk*256 + kb*16 + 2*tig;
    unsigned bh0, bl0, bh1, bl1;
    split2(pw[base],     pw[base + 1], bh0, bl0);
    split2(pw[base + 8], pw[base + 9], bh1, bl1);
    g_Wm4[idx] = make_float4(__uint_as_float(bh0), __uint_as_float(bh1),
                             __uint_as_float(bl0), __uint_as_float(bl1));
}

// ---------------- prep: per-tile A-fragments for att GEMM ----------------
__global__ void k_prepA(){
    int idx = blockIdx.x*256 + threadIdx.x;    // NTILE*4*16*32
    int lane = idx & 31;
    int kb   = (idx >> 5) & 15;
    int ma   = (idx >> 9) & 3;
    int tile = idx >> 11;
    const float* src = (tile < NSUP) ? (g_sN + (size_t)tile*TILE_ELEMS)
                                     : (g_qN + (size_t)(tile-NSUP)*TILE_ELEMS);
    int gid = lane >> 2, tig = lane & 3;
    unsigned h[4], l[4];
    #pragma unroll
    for (int p = 0; p < 4; p++){
        int row = ma*16 + gid + (p & 1)*8;
        int col = kb*16 + 2*tig + (p >> 1)*8;
        split2(src[row*D + col], src[row*D + col + 1], h[p], l[p]);
    }
    g_AspH[idx] = make_uint4(h[0], h[1], h[2], h[3]);
    g_AspL[idx] = make_uint4(l[0], l[1], l[2], l[3]);
}

// ---------------- prep: per-tile B-fragments (n=seq,k=d) for att GEMM ----------------
__global__ void k_prepB(){
    int idx = blockIdx.x*256 + threadIdx.x;    // NTILE*8*16*32
    int lane = idx & 31;
    int kb   = (idx >> 5) & 15;
    int n8   = (idx >> 9) & 7;
    int tile = idx >> 12;
    const float* src = (tile < NSUP) ? (g_sN + (size_t)tile*TILE_ELEMS)
                                     : (g_qN + (size_t)(tile-NSUP)*TILE_ELEMS);
    int gid = lane >> 2, tig = lane & 3;
    int row = n8*8 + gid;
    int col = kb*16 + 2*tig;
    unsigned bh0, bl0, bh1, bl1;
    split2(src[row*D + col],     src[row*D + col + 1], bh0, bl0);
    split2(src[row*D + col + 8], src[row*D + col + 9], bh1, bl1);
    g_BspS[idx] = make_uint4(bh0, bh1, bl0, bl1);
}

// ---------------- prep: per-tile B-fragments (n=d,k=seq) for pv GEMM ----------------
__global__ void k_prepXD(){
    int idx = blockIdx.x*256 + threadIdx.x;    // NTILE*256*32
    int kp = idx & 31;
    int d  = (idx >> 5) & 255;
    int tile = idx >> 13;
    const float* src = (tile < NSUP) ? (g_sN + (size_t)tile*TILE_ELEMS)
                                     : (g_qN + (size_t)(tile-NSUP)*TILE_ELEMS);
    unsigned h, l;
    split2(src[(2*kp)*D + d], src[(2*kp + 1)*D + d], h, l);
    g_XspD[idx] = make_uint2(h, l);
}

// ---------------- kernel C: per-tile base (fragment layout) + Y1 = x@W1blk ----------------
__global__ void __launch_bounds__(256,1) k_base(const float* __restrict__ pb){
    extern __shared__ float smx[];
    int tile = blockIdx.x, t = threadIdx.x;
    const float* src = (tile < NSUP) ? (g_sN + (size_t)tile*TILE_ELEMS)
                                     : (g_qN + (size_t)(tile-NSUP)*TILE_ELEMS);
    for (int idx = t; idx < TILE_ELEMS; idx += 256){
        int row = idx >> 8, col = idx & 255;
        smx[row*PITCH + col] = src[idx];
    }
    __syncthreads();

    const int lane = t & 31, warp = t >> 5;
    const int gid = lane >> 2, tig = lane & 3;
    const int wm = warp >> 2, wn = warp & 3;

    // pass 1: base = x @ W0^T + b
    {
        float c[2][8][4];
        #pragma unroll
        for (int nt = 0; nt < 8; nt++){
            int col = wn*64 + nt*8 + 2*tig;
            float b0 = pb[col], b1 = pb[col+1];
            #pragma unroll
            for (int mt = 0; mt < 2; mt++){
                c[mt][nt][0] = b0; c[mt][nt][1] = b1;
                c[mt][nt][2] = b0; c[mt][nt][3] = b1;
            }
        }
        for (int kb = 0; kb < 16; kb++){
            unsigned ah[2][4], al[2][4];
            #pragma unroll
            for (int mt = 0; mt < 2; mt++){
                int r0 = wm*32 + mt*16 + gid;
                int c0 = kb*16 + 2*tig;
                #pragma unroll
                for (int p = 0; p < 4; p++){
                    float2 x2 = *(const float2*)(smx + (r0 + (p & 1)*8)*PITCH + c0 + (p >> 1)*8);
                    split2(x2.x, x2.y, ah[mt][p], al[mt][p]);
                }
            }
            #pragma unroll
            for (int nt = 0; nt < 8; nt++){
                float4 wv = __ldg(&g_Wm4[((kb*4 + 3)*32 + wn*8 + nt)*32 + lane]);
                unsigned bh[2] = { __float_as_uint(wv.x), __float_as_uint(wv.y) };
                unsigned bl[2] = { __float_as_uint(wv.z), __float_as_uint(wv.w) };
                mma3(c[0][nt], ah[0], al[0], bh, bl);
                mma3(c[1][nt], ah[1], al[1], bh, bl);
            }
        }
        #pragma unroll
        for (int mt = 0; mt < 2; mt++){
            int r16 = wm*2 + mt;
            #pragma unroll
            for (int nt = 0; nt < 8; nt++){
                int j8 = wn*8 + nt;
                g_baseF[((tile*4 + r16)*32 + j8)*32 + lane] =
                    make_float4(c[mt][nt][0], c[mt][nt][1], c[mt][nt][2], c[mt][nt][3]);
            }
        }
    }

    // pass 2: Y1 = x @ W1blk^T
    {
        float c[2][8][4];
        #pragma unroll
        for (int mt = 0; mt < 2; mt++)
            #pragma unroll
            for (int nt = 0; nt < 8; nt++)
                #pragma unroll
                for (int i = 0; i < 4; i++) c[mt][nt][i] = 0.f;
        for (int kb = 0; kb < 16; kb++){
            unsigned ah[2][4], al[2][4];
            #pragma unroll
            for (int mt = 0; mt < 2; mt++){
                int r0 = wm*32 + mt*16 + gid;
                int c0 = kb*16 + 2*tig;
                #pragma unroll
                for (int p = 0; p < 4; p++){
                    float2 x2 = *(const float2*)(smx + (r0 + (p & 1)*8)*PITCH + c0 + (p >> 1)*8);
                    split2(x2.x, x2.y, ah[mt][p], al[mt][p]);
                }
            }
            #pragma unroll
            for (int nt = 0; nt < 8; nt++){
                float4 wv = __ldg(&g_Wm4[((kb*4 + 0)*32 + wn*8 + nt)*32 + lane]);
                unsigned bh[2] = { __float_as_uint(wv.x), __float_as_uint(wv.y) };
                unsigned bl[2] = { __float_as_uint(wv.z), __float_as_uint(wv.w) };
                mma3(c[0][nt], ah[0], al[0], bh, bl);
                mma3(c[1][nt], ah[1], al[1], bh, bl);
            }
        }
        float* dst = g_Y1f + (size_t)tile*TILE_ELEMS;
        #pragma unroll
        for (int mt = 0; mt < 2; mt++){
            int r0 = wm*32 + mt*16 + gid;
            #pragma unroll
            for (int nt = 0; nt < 8; nt++){
                int col = wn*64 + nt*8 + 2*tig;
                *(float2*)(dst + r0*D + col)     = make_float2(c[mt][nt][0], c[mt][nt][1]);
                *(float2*)(dst + (r0+8)*D + col) = make_float2(c[mt][nt][2], c[mt][nt][3]);
            }
        }
    }
}

// ---------------- kernel C2: split Y1 along seq dim -> g_Y1sp[tile][d][kpair] ----------------
__global__ void k_prepY1(){
    int idx = blockIdx.x*256 + threadIdx.x;   // NTILE*8192
    int tile = idx >> 13;
    int rem  = idx & 8191;
    int d  = rem >> 5;
    int kp = rem & 31;
    const float* Y = g_Y1f + (size_t)tile*TILE_ELEMS;
    float y0 = Y[(2*kp)*D + d];
    float y1 = Y[(2*kp+1)*D + d];
    unsigned h, l; split2(y0, y1, h, l);
    g_Y1sp[idx] = make_uint2(h, l);
}

// ---------------- kernel D: one CTA per (pair, side); side 0 = S-phase, 1 = Q-phase -------
__global__ void __launch_bounds__(256, 2) k_pair(
    const float* __restrict__ ln2g, const float* __restrict__ ln2b)
{
    extern __shared__ float sm[];
    float* a_t  = sm + SM_A;
    float* att  = sm + SM_ATT;
    float* pmax = sm + SM_PMAX;
    float* psum = sm + SM_PSUM;
    float* pool = sm + SM_POOL;
    float* scal = sm + SM_SCAL;
    float* red  = sm + SM_RED;

    const int bid = blockIdx.x;
    const int m = bid >> 1, side = bid & 1;   // side 0 = S, 1 = Q
    const int b = m / (NQh*Nh);
    const int rem = m % (NQh*Nh);
    const int iq = rem / Nh;
    const int n  = rem % Nh;
    const int sIdx = b*Nh + n;
    const int qIdx = b*NQh + iq;
    const int qTile = NSUP + qIdx;
    const int t = threadIdx.x;
    const int lane = t & 31, warp = t >> 5;
    const int gid = lane >> 2, tig = lane & 3;

    // -------- att[l][k] = s[l] . q[k]  (8 warps: 4x2 grid; warp tile 16x32) --------
    {
        const int wma = warp >> 1, wna = warp & 1;
        float ca[4][4];
        #pragma unroll
        for (int nt = 0; nt < 4; nt++)
            #pragma unroll
            for (int i = 0; i < 4; i++) ca[nt][i] = 0.f;
        const uint4* aspH = g_AspH + ((size_t)sIdx*4 + wma)*16*32;
        const uint4* aspL = g_AspL + ((size_t)sIdx*4 + wma)*16*32;
        for (int kb = 0; kb < 16; kb++){
            uint4 AH = __ldg(&aspH[kb*32 + lane]);
            uint4 AL = __ldg(&aspL[kb*32 + lane]);
            unsigned ah[4] = { AH.x, AH.y, AH.z, AH.w };
            unsigned al[4] = { AL.x, AL.y, AL.z, AL.w };
            #pragma unroll
            for (int nt = 0; nt < 4; nt++){
                int n8 = wna*4 + nt;
                uint4 B = __ldg(&g_BspS[(((size_t)qTile*8 + n8)*16 + kb)*32 + lane]);
                unsigned bh[2] = { B.x, B.y };
                unsigned bl[2] = { B.z, B.w };
                mma3(ca[nt], ah, al, bh, bl);
            }
        }
        #pragma unroll
        for (int nt = 0; nt < 4; nt++){
            int r0 = wma*16 + gid;
            int col = (wna*4 + nt)*8 + 2*tig;
            *(float2*)(att + r0*PA + col)     = make_float2(ca[nt][0], ca[nt][1]);
            *(float2*)(att + (r0+8)*PA + col) = make_float2(ca[nt][2], ca[nt][3]);
        }
    }
    __syncthreads();

    // -------- softmax (one direction only) --------
    if (side == 0){
        // row softmax: att := exp(att - rowmax); scal = 1/rowsum
        int row = t >> 2, sub = t & 3;
        float* rp = att + row*PA + sub*16;
        float mx = -3.4e38f;
        #pragma unroll
        for (int i = 0; i < 16; i++) mx = fmaxf(mx, rp[i]);
        mx = fmaxf(mx, __shfl_xor_sync(0xffffffffu, mx, 1));
        mx = fmaxf(mx, __shfl_xor_sync(0xffffffffu, mx, 2));
        float s = 0.f;
        #pragma unroll
        for (int i = 0; i < 16; i++){
            float e = __expf(rp[i] - mx);
            rp[i] = e; s += e;
        }
        s += __shfl_xor_sync(0xffffffffu, s, 1);
        s += __shfl_xor_sync(0xffffffffu, s, 2);
        if (sub == 0) scal[row] = 1.0f / s;
    } else {
        // column softmax (unnormalized): att := exp(att - colmax); scal = 1/colsum
        int col = t >> 2, sub = t & 3;
        float mx = -3.4e38f;
        #pragma unroll
        for (int i = 0; i < 16; i++) mx = fmaxf(mx, att[(sub*16 + i)*PA + col]);
        mx = fmaxf(mx, __shfl_xor_sync(0xffffffffu, mx, 1));
        mx = fmaxf(mx, __shfl_xor_sync(0xffffffffu, mx, 2));
        float s = 0.f;
        #pragma unroll
        for (int i = 0; i < 16; i++){
            int l = sub*16 + i;
            float e = __expf(att[l*PA + col] - mx);
            att[l*PA + col] = e; s += e;
        }
        s += __shfl_xor_sync(0xffffffffu, s, 1);
        s += __shfl_xor_sync(0xffffffffu, s, 2);
        if (sub == 0) scal[col] = 1.0f / s;
    }
    __syncthreads();

    // -------- pv + y1: a_t = scal * (A @ X);  scratch = base + scal * (A @ Y1) --------
    // side 0: A = E (transA=0), X/Y1 = q tile, out rows = s rows, scal = 1/rowsum
    // side 1: A = expcol^T (transA=1), X/Y1 = s tile, out rows = q rows, scal = 1/colsum
    {
        const int wm = warp >> 2, wn = warp & 3;
        const int bTile = side ? sIdx : qTile;      // x / y1 source tile
        const int baseTile = side ? qTile : sIdx;   // proj base tile (own side)
        const uint2* xsp = g_XspD + (size_t)bTile*8192;
        const uint2* ysp = g_Y1sp + (size_t)bTile*8192;

        // stage all A fragments for this warp's 32 rows (K = 64)
        unsigned ah[4][2][4], al[4][2][4];
        #pragma unroll
        for (int kb = 0; kb < 4; kb++)
            #pragma unroll
            for (int mt = 0; mt < 2; mt++)
                #pragma unroll
                for (int p = 0; p < 4; p++){
                    int rr = wm*32 + mt*16 + gid + (p & 1)*8;
                    int cc = kb*16 + 2*tig + (p >> 1)*8;
                    float v0, v1;
                    if (side){ v0 = att[cc*PA + rr]; v1 = att[(cc+1)*PA + rr]; }
                    else { float2 v = *(const float2*)(att + rr*PA + cc); v0 = v.x; v1 = v.y; }
                    split2(v0, v1, ah[kb][mt][p], al[kb][mt][p]);
                }

        float s0 = scal[wm*32 + gid];       // row scale for mt=0 rows (r0)
        float s0b = scal[wm*32 + gid + 8];
        float s1 = scal[wm*32 + 16 + gid];
        float s1b = scal[wm*32 + 16 + gid + 8];

        for (int nt = 0; nt < 8; nt++){
            float c[2][4], c2[2][4];
            #pragma unroll
            for (int mt = 0; mt < 2; mt++)
                #pragma unroll
                for (int i = 0; i < 4; i++){ c[mt][i] = 0.f; c2[mt][i] = 0.f; }
            int d0 = wn*64 + nt*8 + gid;
            #pragma unroll
            for (int kb = 0; kb < 4; kb++){
                int kp = kb*8 + tig;
                uint2 xu0 = __ldg(&xsp[d0*32 + kp]);
                uint2 xu1 = __ldg(&xsp[d0*32 + kp + 4]);
                uint2 yu0 = __ldg(&ysp[d0*32 + kp]);
                uint2 yu1 = __ldg(&ysp[d0*32 + kp + 4]);
                unsigned bhx[2] = { xu0.x, xu1.x }, blx[2] = { xu0.y, xu1.y };
                unsigned bhy[2] = { yu0.x, yu1.x }, bly[2] = { yu0.y, yu1.y };
                mma3(c[0],  ah[kb][0], al[kb][0], bhx, blx);
                mma3(c[1],  ah[kb][1], al[kb][1], bhx, blx);
                mma3(c2[0], ah[kb][0], al[kb][0], bhy, bly);
                mma3(c2[1], ah[kb][1], al[kb][1], bhy, bly);
            }
            int col = wn*64 + nt*8 + 2*tig;
            {
                int r0 = wm*32 + gid;
                *(float2*)(a_t + r0*PITCH + col)     = make_float2(c[0][0]*s0,  c[0][1]*s0);
                *(float2*)(a_t + (r0+8)*PITCH + col) = make_float2(c[0][2]*s0b, c[0][3]*s0b);
                int r1 = wm*32 + 16 + gid;
                *(float2*)(a_t + r1*PITCH + col)     = make_float2(c[1][0]*s1,  c[1][1]*s1);
                *(float2*)(a_t + (r1+8)*PITCH + col) = make_float2(c[1][2]*s1b, c[1][3]*s1b);
            }
            #pragma unroll
            for (int mt = 0; mt < 2; mt++){
                float sa = (mt == 0) ? s0 : s1;
                float sb = (mt == 0) ? s0b : s1b;
                int fi = ((baseTile*4 + wm*2 + mt)*32 + wn*8 + nt)*32 + lane;
                float4 bv = __ldg(&g_baseF[fi]);
                g_c2scr[((size_t)bid*4 + wm*2 + mt)*1024 + (wn*8 + nt)*32 + lane] =
                    make_float4(bv.x + c2[mt][0]*sa, bv.y + c2[mt][1]*sa,
                                bv.z + c2[mt][2]*sb, bv.w + c2[mt][3]*sb);
            }
        }
    }
    __syncthreads();

    // -------- proj (2 features) + mish + pool, two nt-halves to cap registers --------
    {
        const int wm = warp >> 2, wn = warp & 3;
        const float* xg = side ? (g_qN + (size_t)qIdx*TILE_ELEMS)
                               : (g_sN + (size_t)sIdx*TILE_ELEMS);
        float mymax[8][2], mysum[8][2];

        #pragma unroll
        for (int h = 0; h < 2; h++){
            float c[2][4][4];
            #pragma unroll
            for (int mt = 0; mt < 2; mt++)
                #pragma unroll
                for (int nt = 0; nt < 4; nt++){
                    float4 v = g_c2scr[((size_t)bid*4 + wm*2 + mt)*1024 +
                                       (wn*8 + h*4 + nt)*32 + lane];
                    c[mt][nt][0] = v.x; c[mt][nt][1] = v.y;
                    c[mt][nt][2] = v.z; c[mt][nt][3] = v.w;
                }

            for (int kb = 0; kb < 16; kb++){
                float2 xv[2][4], av[2][4];
                #pragma unroll
                for (int mt = 0; mt < 2; mt++){
                    int r0 = wm*32 + mt*16 + gid;
                    int c0 = kb*16 + 2*tig;
                    #pragma unroll
                    for (int p = 0; p < 4; p++){
                        int rr = r0 + (p & 1)*8;
                        int cc = c0 + (p >> 1)*8;
                        xv[mt][p] = __ldg((const float2*)(xg + rr*D + cc));
                        av[mt][p] = *(const float2*)(a_t + rr*PITCH + cc);
                    }
                }
                // feature |x - a|
                {
                    unsigned ah[2][4], al[2][4];
                    #pragma unroll
                    for (int mt = 0; mt < 2; mt++)
                        #pragma unroll
                        for (int p = 0; p < 4; p++)
                            split2(fabsf(xv[mt][p].x - av[mt][p].x),
                                   fabsf(xv[mt][p].y - av[mt][p].y), ah[mt][p], al[mt][p]);
                    #pragma unroll
                    for (int nt = 0; nt < 4; nt++){
                        float4 wv = __ldg(&g_Wm4[((kb*4 + 1)*32 + wn*8 + h*4 + nt)*32 + lane]);
                        unsigned bh[2] = { __float_as_uint(wv.x), __float_as_uint(wv.y) };
                        unsigned bl[2] = { __float_as_uint(wv.z), __float_as_uint(wv.w) };
                        mma3(c[0][nt], ah[0], al[0], bh, bl);
                        mma3(c[1][nt], ah[1], al[1], bh, bl);
                    }
                }
                // feature x * a
                {
                    unsigned ah[2][4], al[2][4];
                    #pragma unroll
                    for (int mt = 0; mt < 2; mt++)
                        #pragma unroll
                        for (int p = 0; p < 4; p++)
                            split2(xv[mt][p].x * av[mt][p].x,
                                   xv[mt][p].y * av[mt][p].y, ah[mt][p], al[mt][p]);
                    #pragma unroll
                    for (int nt = 0; nt < 4; nt++){
                        float4 wv = __ldg(&g_Wm4[((kb*4 + 2)*32 + wn*8 + h*4 + nt)*32 + lane]);
                        unsigned bh[2] = { __float_as_uint(wv.x), __float_as_uint(wv.y) };
                        unsigned bl[2] = { __float_as_uint(wv.z), __float_as_uint(wv.w) };
                        mma3(c[0][nt], ah[0], al[0], bh, bl);
                        mma3(c[1][nt], ah[1], al[1], bh, bl);
                    }
                }
            }

            // mish + per-column max/sum (reduce over gid rows within warp)
            #pragma unroll
            for (int nt = 0; nt < 4; nt++){
                #pragma unroll
                for (int e = 0; e < 2; e++){
                    float v00 = mishf(c[0][nt][e]);
                    float v01 = mishf(c[0][nt][2+e]);
                    float v10 = mishf(c[1][nt][e]);
                    float v11 = mishf(c[1][nt][2+e]);
                    float mx = fmaxf(fmaxf(v00, v01), fmaxf(v10, v11));
                    float smv = (v00 + v01) + (v10 + v11);
                    #pragma unroll
                    for (int off = 4; off < 32; off <<= 1){
                        mx = fmaxf(mx, __shfl_xor_sync(0xffffffffu, mx, off));
                        smv += __shfl_xor_sync(0xffffffffu, smv, off);
                    }
                    mymax[h*4 + nt][e] = mx; mysum[h*4 + nt][e] = smv;
                }
            }
        }

        if (wm == 1 && gid == 0){
            #pragma unroll
            for (int nt8 = 0; nt8 < 8; nt8++)
                #pragma unroll
                for (int e = 0; e < 2; e++){
                    int j = wn*64 + nt8*8 + 2*tig + e;
                    pmax[j] = mymax[nt8][e]; psum[j] = mysum[nt8][e];
                }
        }
        __syncthreads();
        if (wm == 0 && gid == 0){
            #pragma unroll
            for (int nt8 = 0; nt8 < 8; nt8++)
                #pragma unroll
                for (int e = 0; e < 2; e++){
                    int j = wn*64 + nt8*8 + 2*tig + e;
                    pool[j]     = fmaxf(mymax[nt8][e], pmax[j]);
                    pool[D + j] = (mysum[nt8][e] + psum[j]) * (1.0f/(float)Lh);
                }
        }
        __syncthreads();
    }

    // -------- LayerNorm over 512 (2 elems per thread) + store to g_pool --------
    {
        float v0 = pool[t], v1 = pool[t + 256];
        float S  = blockSum256(v0 + v1,       red, t);
        float SS = blockSum256(v0*v0 + v1*v1, red, t);
        float mean = S  * (1.0f/512.0f);
        float var  = SS * (1.0f/512.0f) - mean*mean;
        float inv  = rsqrtf(var + 1e-5f);
        int off = side ? 0 : 512;     // cat = [q_pool | s_pool]
        g_pool[(size_t)m*1024 + off + t]       = (v0 - mean)*inv*ln2g[t]       + ln2b[t];
        g_pool[(size_t)m*1024 + off + 256 + t] = (v1 - mean)*inv*ln2g[256 + t] + ln2b[256 + t];
    }
}

// ---------------- kernel H: batched MLP head (8 pairs per block) ----------------
__global__ void __launch_bounds__(256) k_head(
    const float* __restrict__ b1v, const float* __restrict__ W2,
    const float* __restrict__ b2,  const float* __restrict__ W3,
    const float* __restrict__ b3)
{
    __shared__ float ps[8*1024];
    __shared__ float red[8][8];
    int t = threadIdx.x;
    int m0 = blockIdx.x*8;
    for (int i = t; i < 8*1024; i += 256) ps[i] = g_pool[(size_t)m0*1024 + i];
    __syncthreads();
    float acc[8];
    #pragma unroll
    for (int r = 0; r < 8; r++) acc[r] = 0.f;
    #pragma unroll 4
    for (int c = 0; c < 1024; c++){
        float w = g_W1T[c*D + t];
        #pragma unroll
        for (int r = 0; r < 8; r++) acc[r] += ps[r*1024 + c]*w;
    }
    float b1j = b1v[t], w2j = W2[t];
    #pragma unroll
    for (int r = 0; r < 8; r++){
        float part = mishf(acc[r] + b1j) * w2j;
        #pragma unroll
        for (int o = 16; o > 0; o >>= 1) part += __shfl_xor_sync(0xffffffffu, part, o);
        if ((t & 31) == 0) red[r][t >> 5] = part;
    }
    __syncthreads();
    if (t < 8){
        float tot = 0.f;
        #pragma unroll
        for (int w = 0; w < 8; w++) tot += red[t][w];
        g_logits[m0 + t] = mishf(tot + b2[0])*W3[0] + b3[0];
    }
}

// ---------------- kernel E: min-append, logits layout, argmax ----------------
__global__ void k_final(float* __restrict__ out, int out_size){
    int u = threadIdx.x;
    if (u >= Bh*NQh) return;
    float v[Nh];
    float mn = 3.4e38f;
    #pragma unroll
    for (int n2 = 0; n2 < Nh; n2++){
        v[n2] = g_logits[u*Nh + n2];
        mn = fminf(mn, v[n2]);
    }
    if (out_size >= 1100){
        float best = -3.4e38f; int bi = 0;
        #pragma unroll
        for (int n2 = 0; n2 < Nh; n2++){
            out[u*(Nh+1) + n2] = v[n2];
            if (v[n2] > best){ best = v[n2]; bi = n2; }
        }
        out[u*(Nh+1) + Nh] = mn - 1.0f;
        if (out_size >= 1200) out[Bh*NQh*(Nh+1) + u] = (float)bi;
    } else if (out_size == Bh*NQh){
        float best = -3.4e38f; int bi = 0;
        #pragma unroll
        for (int n2 = 0; n2 < Nh; n2++)
            if (v[n2] > best){ best = v[n2]; bi = n2; }
        ((int*)out)[u] = bi;
    }
}

// ---------------- launch ----------------
extern "C" void kernel_launch(void* const* d_in, const int* in_sizes, int n_in,
                              void* d_out, int out_size)
{
    const float* support = (const float*)d_in[0];
    const float* query   = (const float*)d_in[1];
    const float* ln_g    = (const float*)d_in[2];
    const float* ln_b    = (const float*)d_in[3];
    const float* ln2_g   = (const float*)d_in[4];
    const float* ln2_b   = (const float*)d_in[5];
    const float* proj_W  = (const float*)d_in[6];
    const float* proj_b  = (const float*)d_in[7];
    const float* W1      = (const float*)d_in[8];
    const float* b1      = (const float*)d_in[9];
    const float* W2      = (const float*)d_in[10];
    const float* b2      = (const float*)d_in[11];
    const float* W3      = (const float*)d_in[12];
    const float* b3      = (const float*)d_in[13];

    cudaFuncSetAttribute(k_pair, cudaFuncAttributeMaxDynamicSharedMemorySize, SMEM_PAIR_BYTES);
    cudaFuncSetAttribute(k_base, cudaFuncAttributeMaxDynamicSharedMemorySize, SMEM_BASE_BYTES);

    k_ln<<<(NSUP + NQRY)*Lh, 256>>>(support, query, ln_g, ln_b);
    k_transposeW1<<<1024, 256>>>(W1);
    k_prepw<<<256, 256>>>(proj_W);
    k_prepA<<<NTILE*8, 256>>>();
    k_prepB<<<NTILE*16, 256>>>();
    k_prepXD<<<NTILE*32, 256>>>();
    k_base<<<NTILE, 256, SMEM_BASE_BYTES>>>(proj_b);
    k_prepY1<<<NTILE*32, 256>>>();
    k_pair<<<2*Mh, 256, SMEM_PAIR_BYTES>>>(ln2_g, ln2_b);
    k_head<<<Mh/8, 256>>>(b1, W2, b2, W3, b3);
    k_final<<<1, 128>>>((float*)d_out, out_size);
}